// round 6
// baseline (speedup 1.0000x reference)
#include <cuda_runtime.h>
#include <cuda_bf16.h>
#include <cstdint>

#define NN 100000
#define DD 128
#define GG 64

// Scratch (__device__ globals; no allocation allowed)
__device__ __align__(16) float g_h0[NN * DD];
__device__ __align__(16) float g_h1[NN * DD];
__device__ __align__(16) float g_h2[NN * DD];
__device__ __align__(16) float g_wt[3 * DD * DD];   // W transposed + tf32-rounded: wt[l][n][k]
__device__ float g_cs[NN];
__device__ float g_cd[NN];
__device__ int   g_degout[NN];
__device__ int   g_degin[NN];
__device__ int   g_rowstart[NN];
__device__ int   g_cursor[NN];
__device__ int   g_csr[1700000];
__device__ __align__(16) float g_sums[GG * DD];
__device__ float g_cnt[GG];

__device__ __forceinline__ float to_tf32(float x) {
    float r;
    asm("cvt.rna.tf32.f32 %0, %1;" : "=f"(r) : "f"(x));
    return r;
}

// ---------------------------------------------------------------------------
// Setup: zero int arrays + pool accumulators, prep all 3 W (transpose + tf32)
// ---------------------------------------------------------------------------
__global__ void setup_kernel(const float* __restrict__ W0, const float* __restrict__ W1,
                             const float* __restrict__ W2, int n) {
    int i = blockIdx.x * blockDim.x + threadIdx.x;
    if (i < n) { g_degout[i] = 0; g_degin[i] = 0; g_cursor[i] = 0; }
    if (i < 3 * DD * DD) {
        const float* W = (i < DD * DD) ? W0 : ((i < 2 * DD * DD) ? W1 : W2);
        int j = i & (DD * DD - 1);
        int k = j >> 7, nn = j & 127;
        g_wt[(i >> 14) * DD * DD + nn * DD + k] = to_tf32(W[j]);
    }
    if (i < GG * DD) g_sums[i] = 0.0f;
    if (i < GG) g_cnt[i] = 0.0f;
}

__global__ void count_deg_kernel(const int* __restrict__ src,
                                 const int* __restrict__ dst, int e) {
    int i = blockIdx.x * blockDim.x + threadIdx.x;
    if (i < e) {
        atomicAdd(&g_degout[src[i]], 1);
        atomicAdd(&g_degin[dst[i]], 1);
    }
}

// Single-CTA scan over degin -> rowstart, plus norms. 1024 threads.
__global__ void norm_scan_kernel(int n) {
    __shared__ int s[1024];
    int t = threadIdx.x;
    int chunk = (n + 1023) >> 10;
    int lo = min(t * chunk, n), hi = min(lo + chunk, n);
    int sum = 0;
    for (int i = lo; i < hi; i++) sum += g_degin[i];
    s[t] = sum;
    __syncthreads();
#pragma unroll
    for (int off = 1; off < 1024; off <<= 1) {
        int add = (t >= off) ? s[t - off] : 0;
        __syncthreads();
        s[t] += add;
        __syncthreads();
    }
    int run = s[t] - sum;   // exclusive
    for (int i = lo; i < hi; i++) { g_rowstart[i] = run; run += g_degin[i]; }
    for (int i = t; i < n; i += 1024) {
        g_cs[i] = rsqrtf((float)(g_degout[i] + 1));
        g_cd[i] = rsqrtf((float)(g_degin[i] + 1));
    }
}

__global__ void fill_csr_kernel(const int* __restrict__ src,
                                const int* __restrict__ dst, int e) {
    int i = blockIdx.x * blockDim.x + threadIdx.x;
    if (i < e) {
        int d = dst[i];
        int pos = atomicAdd(&g_cursor[d], 1);
        g_csr[g_rowstart[d] + pos] = src[i];
    }
}

// ---------------------------------------------------------------------------
// Fused layer: gather (CSR, warp-per-node) -> smem A tile (tf32) -> tensor MMA
// out = relu( (cd*(sum hs)) @ W + b ) [ * cs[row] if cs_out ]
// CS_IN: input rows must be scaled by cs[src] on the fly (layer 0 / raw x).
// 512 threads: 16 warps. Gather: warp w handles rows w*8..w*8+7.
// MMA: 4x4 warp grid, warp tile 32x32 (2x4 m16n8k8).
// ---------------------------------------------------------------------------
#define GSTR 132
#define FT_SMEM (2 * 128 * GSTR * 4)

template <bool CS_IN>
__global__ void __launch_bounds__(512, 1)
fused_layer_kernel(const float* __restrict__ hin, const float* __restrict__ wt,
                   const float* __restrict__ b, float* __restrict__ out,
                   int n, int cs_out) {
    extern __shared__ float sh[];
    float* Bsm = sh;               // 128 x GSTR : Wt[n][k] (tf32)
    float* Asm = sh + 128 * GSTR;  // 128 x GSTR : gathered A rows (tf32)

    int t = threadIdx.x;
    int wid = t >> 5, lane = t & 31;
    int rows0 = blockIdx.x * 128;

    // Stage Wt
#pragma unroll
    for (int it = 0; it < 8; it++) {
        int e4 = t + it * 512;
        int r = e4 >> 5, kq = e4 & 31;
        *(float4*)&Bsm[r * GSTR + kq * 4] = __ldg((const float4*)wt + e4);
    }

    // Gather phase: warp handles 8 nodes
    for (int ni = 0; ni < 8; ni++) {
        int r = wid * 8 + ni;
        int node = rows0 + r;
        if (node > n - 1) node = n - 1;
        int base = g_rowstart[node];
        int deg  = g_degin[node];

        float4 acc = __ldg((const float4*)hin + (size_t)node * 32 + lane);
        if (CS_IN) {
            float c = g_cs[node];
            acc.x *= c; acc.y *= c; acc.z *= c; acc.w *= c;
        }

        for (int j0 = 0; j0 < deg; j0 += 32) {
            int cnt = min(32, deg - j0);
            int sj = 0; float cj = 0.0f;
            if (lane < cnt) {
                sj = __ldg(&g_csr[base + j0 + lane]);
                if (CS_IN) cj = g_cs[sj];
            }
            int k = 0;
            for (; k + 4 <= cnt; k += 4) {
                int s0 = __shfl_sync(0xffffffffu, sj, k);
                int s1 = __shfl_sync(0xffffffffu, sj, k + 1);
                int s2 = __shfl_sync(0xffffffffu, sj, k + 2);
                int s3 = __shfl_sync(0xffffffffu, sj, k + 3);
                float4 v0 = __ldg((const float4*)hin + (size_t)s0 * 32 + lane);
                float4 v1 = __ldg((const float4*)hin + (size_t)s1 * 32 + lane);
                float4 v2 = __ldg((const float4*)hin + (size_t)s2 * 32 + lane);
                float4 v3 = __ldg((const float4*)hin + (size_t)s3 * 32 + lane);
                if (CS_IN) {
                    float c0 = __shfl_sync(0xffffffffu, cj, k);
                    float c1 = __shfl_sync(0xffffffffu, cj, k + 1);
                    float c2 = __shfl_sync(0xffffffffu, cj, k + 2);
                    float c3 = __shfl_sync(0xffffffffu, cj, k + 3);
                    acc.x += v0.x * c0; acc.y += v0.y * c0; acc.z += v0.z * c0; acc.w += v0.w * c0;
                    acc.x += v1.x * c1; acc.y += v1.y * c1; acc.z += v1.z * c1; acc.w += v1.w * c1;
                    acc.x += v2.x * c2; acc.y += v2.y * c2; acc.z += v2.z * c2; acc.w += v2.w * c2;
                    acc.x += v3.x * c3; acc.y += v3.y * c3; acc.z += v3.z * c3; acc.w += v3.w * c3;
                } else {
                    acc.x += v0.x + v1.x + v2.x + v3.x;
                    acc.y += v0.y + v1.y + v2.y + v3.y;
                    acc.z += v0.z + v1.z + v2.z + v3.z;
                    acc.w += v0.w + v1.w + v2.w + v3.w;
                }
            }
            for (; k < cnt; k++) {
                int s0 = __shfl_sync(0xffffffffu, sj, k);
                float4 v0 = __ldg((const float4*)hin + (size_t)s0 * 32 + lane);
                if (CS_IN) {
                    float c0 = __shfl_sync(0xffffffffu, cj, k);
                    acc.x += v0.x * c0; acc.y += v0.y * c0; acc.z += v0.z * c0; acc.w += v0.w * c0;
                } else {
                    acc.x += v0.x; acc.y += v0.y; acc.z += v0.z; acc.w += v0.w;
                }
            }
        }

        float cdv = g_cd[node];
        acc.x = to_tf32(acc.x * cdv); acc.y = to_tf32(acc.y * cdv);
        acc.z = to_tf32(acc.z * cdv); acc.w = to_tf32(acc.w * cdv);
        *(float4*)&Asm[r * GSTR + lane * 4] = acc;
    }
    __syncthreads();

    // MMA phase: 16 warps, 4(M) x 4(N) warp grid, warp tile 32x32
    int groupID = lane >> 2, ktid = lane & 3;
    int warpM = (wid & 3) * 32;
    int warpN = (wid >> 2) * 32;

    float acc2[2][4][4];
#pragma unroll
    for (int mt = 0; mt < 2; mt++)
#pragma unroll
        for (int nt = 0; nt < 4; nt++)
#pragma unroll
            for (int q = 0; q < 4; q++) acc2[mt][nt][q] = 0.0f;

#pragma unroll
    for (int k0 = 0; k0 < 128; k0 += 8) {
        uint32_t a[2][4];
#pragma unroll
        for (int mt = 0; mt < 2; mt++) {
            int r0 = warpM + mt * 16 + groupID;
            a[mt][0] = __float_as_uint(Asm[r0 * GSTR + k0 + ktid]);
            a[mt][1] = __float_as_uint(Asm[(r0 + 8) * GSTR + k0 + ktid]);
            a[mt][2] = __float_as_uint(Asm[r0 * GSTR + k0 + ktid + 4]);
            a[mt][3] = __float_as_uint(Asm[(r0 + 8) * GSTR + k0 + ktid + 4]);
        }
#pragma unroll
        for (int nt = 0; nt < 4; nt++) {
            int c0 = warpN + nt * 8 + groupID;
            uint32_t b0 = __float_as_uint(Bsm[c0 * GSTR + k0 + ktid]);
            uint32_t b1 = __float_as_uint(Bsm[c0 * GSTR + k0 + ktid + 4]);
#pragma unroll
            for (int mt = 0; mt < 2; mt++) {
                asm volatile(
                    "mma.sync.aligned.m16n8k8.row.col.f32.tf32.tf32.f32 "
                    "{%0,%1,%2,%3}, {%4,%5,%6,%7}, {%8,%9}, {%0,%1,%2,%3};"
                    : "+f"(acc2[mt][nt][0]), "+f"(acc2[mt][nt][1]),
                      "+f"(acc2[mt][nt][2]), "+f"(acc2[mt][nt][3])
                    : "r"(a[mt][0]), "r"(a[mt][1]), "r"(a[mt][2]), "r"(a[mt][3]),
                      "r"(b0), "r"(b1));
            }
        }
    }

    // Epilogue: bias + relu (+ optional cs[row] scaling for next layer's gather)
#pragma unroll
    for (int mt = 0; mt < 2; mt++) {
        int r0 = rows0 + warpM + mt * 16 + groupID;
        int r1 = r0 + 8;
        float sc0 = 1.0f, sc1 = 1.0f;
        if (cs_out) {
            if (r0 < n) sc0 = g_cs[r0];
            if (r1 < n) sc1 = g_cs[r1];
        }
#pragma unroll
        for (int nt = 0; nt < 4; nt++) {
            int col = warpN + nt * 8 + 2 * ktid;
            float2 bb = __ldg((const float2*)(b + col));
            if (r0 < n) {
                float2 o;
                o.x = fmaxf(acc2[mt][nt][0] + bb.x, 0.0f) * sc0;
                o.y = fmaxf(acc2[mt][nt][1] + bb.y, 0.0f) * sc0;
                *(float2*)(out + (size_t)r0 * DD + col) = o;
            }
            if (r1 < n) {
                float2 o;
                o.x = fmaxf(acc2[mt][nt][2] + bb.x, 0.0f) * sc1;
                o.y = fmaxf(acc2[mt][nt][3] + bb.y, 0.0f) * sc1;
                *(float2*)(out + (size_t)r1 * DD + col) = o;
            }
        }
    }
}

// ---------------------------------------------------------------------------
// Pooling: graph_ids are sorted -> run-based accumulation, flush per run.
// Warp handles 16 consecutive nodes; lane = float4 column.
// ---------------------------------------------------------------------------
__global__ void pool_kernel(const float* __restrict__ h,
                            const int* __restrict__ gid, int n) {
    int w = (blockIdx.x * blockDim.x + threadIdx.x) >> 5;
    int lane = threadIdx.x & 31;
    int n0 = w * 16;
    if (n0 >= n) return;
    int n1 = min(n0 + 16, n);

    float4 acc = make_float4(0.f, 0.f, 0.f, 0.f);
    int curg = gid[n0];
    int cnt = 0;
    for (int node = n0; node < n1; node++) {
        int g = gid[node];
        if (g != curg) {
            float* o = g_sums + curg * DD + lane * 4;
            asm volatile("red.global.add.v4.f32 [%0], {%1, %2, %3, %4};"
                         :: "l"(o), "f"(acc.x), "f"(acc.y), "f"(acc.z), "f"(acc.w)
                         : "memory");
            if (lane == 0) atomicAdd(&g_cnt[curg], (float)cnt);
            acc = make_float4(0.f, 0.f, 0.f, 0.f);
            curg = g; cnt = 0;
        }
        float4 v = __ldg((const float4*)h + (size_t)node * 32 + lane);
        acc.x += v.x; acc.y += v.y; acc.z += v.z; acc.w += v.w;
        cnt++;
    }
    float* o = g_sums + curg * DD + lane * 4;
    asm volatile("red.global.add.v4.f32 [%0], {%1, %2, %3, %4};"
                 :: "l"(o), "f"(acc.x), "f"(acc.y), "f"(acc.z), "f"(acc.w)
                 : "memory");
    if (lane == 0) atomicAdd(&g_cnt[curg], (float)cnt);
}

__global__ void divide_kernel(float* __restrict__ out) {
    int i = blockIdx.x * blockDim.x + threadIdx.x;
    if (i < GG * DD) out[i] = g_sums[i] / fmaxf(g_cnt[i >> 7], 1.0f);
}

// ---------------------------------------------------------------------------
extern "C" void kernel_launch(void* const* d_in, const int* in_sizes, int n_in,
                              void* d_out, int out_size) {
    const float* x  = (const float*)d_in[0];
    const float* Ws[3] = {(const float*)d_in[1], (const float*)d_in[3], (const float*)d_in[5]};
    const float* bs[3] = {(const float*)d_in[2], (const float*)d_in[4], (const float*)d_in[6]};
    const int* src = (const int*)d_in[7];
    const int* dst = (const int*)d_in[8];
    const int* gid = (const int*)d_in[9];

    int n = in_sizes[0] / DD;          // 100000
    int e = in_sizes[7];               // 1600000

    cudaFuncSetAttribute(fused_layer_kernel<true>,
                         cudaFuncAttributeMaxDynamicSharedMemorySize, FT_SMEM);
    cudaFuncSetAttribute(fused_layer_kernel<false>,
                         cudaFuncAttributeMaxDynamicSharedMemorySize, FT_SMEM);

    void* p0; cudaGetSymbolAddress(&p0, g_h0);
    void* p1; cudaGetSymbolAddress(&p1, g_h1);
    void* p2; cudaGetSymbolAddress(&p2, g_h2);
    void* pw; cudaGetSymbolAddress(&pw, g_wt);
    float* h0 = (float*)p0;
    float* h1 = (float*)p1;
    float* h2 = (float*)p2;
    float* wt = (float*)pw;

    setup_kernel<<<(n + 255) / 256, 256>>>(Ws[0], Ws[1], Ws[2], n);
    count_deg_kernel<<<(e + 255) / 256, 256>>>(src, dst, e);
    norm_scan_kernel<<<1, 1024>>>(n);
    fill_csr_kernel<<<(e + 255) / 256, 256>>>(src, dst, e);

    int gtiles = (n + 127) / 128;
    // layer 0: raw x in (needs cs on gather), out scaled by cs for next gather
    fused_layer_kernel<true><<<gtiles, 512, FT_SMEM>>>(x, wt, bs[0], h0, n, 1);
    // layer 1: hs in, out scaled by cs
    fused_layer_kernel<false><<<gtiles, 512, FT_SMEM>>>(h0, wt + DD * DD, bs[1], h1, n, 1);
    // layer 2: hs in, raw h out (for pooling)
    fused_layer_kernel<false><<<gtiles, 512, FT_SMEM>>>(h1, wt + 2 * DD * DD, bs[2], h2, n, 0);

    pool_kernel<<<(n + 127) / 128, 256>>>(h2, gid, n);
    divide_kernel<<<(GG * DD + 255) / 256, 256>>>((float*)d_out);
}

// round 7
// speedup vs baseline: 1.2896x; 1.2896x over previous
#include <cuda_runtime.h>
#include <cuda_bf16.h>
#include <cstdint>

#define NN 100000
#define DD 128
#define GG 64

// Scratch (__device__ globals; no allocation allowed)
__device__ __align__(16) float g_h0[NN * DD];
__device__ __align__(16) float g_h1[NN * DD];
__device__ __align__(16) float g_h2[NN * DD];
__device__ __align__(16) float g_agg[NN * DD];
__device__ __align__(16) float g_wt[3 * DD * DD];   // W transposed + tf32-rounded
__device__ float g_cs[NN];
__device__ float g_cd[NN];
__device__ int   g_degout[NN];
__device__ int   g_degin[NN];
__device__ int   g_rowstart[NN];
__device__ int   g_cursor[NN];
__device__ int   g_csr[1700000];
__device__ __align__(16) float g_sums[GG * DD];
__device__ float g_cnt[GG];

__device__ __forceinline__ float to_tf32(float x) {
    float r;
    asm("cvt.rna.tf32.f32 %0, %1;" : "=f"(r) : "f"(x));
    return r;
}

// ---------------------------------------------------------------------------
// Setup: zero int arrays + pool accumulators, prep all 3 W (transpose + tf32)
// ---------------------------------------------------------------------------
__global__ void setup_kernel(const float* __restrict__ W0, const float* __restrict__ W1,
                             const float* __restrict__ W2, int n) {
    int i = blockIdx.x * blockDim.x + threadIdx.x;
    if (i < n) { g_degout[i] = 0; g_degin[i] = 0; g_cursor[i] = 0; }
    if (i < 3 * DD * DD) {
        const float* W = (i < DD * DD) ? W0 : ((i < 2 * DD * DD) ? W1 : W2);
        int j = i & (DD * DD - 1);
        int k = j >> 7, nn = j & 127;
        g_wt[(i >> 14) * DD * DD + nn * DD + k] = to_tf32(W[j]);
    }
    if (i < GG * DD) g_sums[i] = 0.0f;
    if (i < GG) g_cnt[i] = 0.0f;
}

__global__ void count_deg_kernel(const int* __restrict__ src,
                                 const int* __restrict__ dst, int e) {
    int i = blockIdx.x * blockDim.x + threadIdx.x;
    if (i < e) {
        atomicAdd(&g_degout[src[i]], 1);
        atomicAdd(&g_degin[dst[i]], 1);
    }
}

// Single-CTA scan over degin -> rowstart, plus norms. 1024 threads.
__global__ void norm_scan_kernel(int n) {
    __shared__ int s[1024];
    int t = threadIdx.x;
    int chunk = (n + 1023) >> 10;
    int lo = min(t * chunk, n), hi = min(lo + chunk, n);
    int sum = 0;
    for (int i = lo; i < hi; i++) sum += g_degin[i];
    s[t] = sum;
    __syncthreads();
#pragma unroll
    for (int off = 1; off < 1024; off <<= 1) {
        int add = (t >= off) ? s[t - off] : 0;
        __syncthreads();
        s[t] += add;
        __syncthreads();
    }
    int run = s[t] - sum;   // exclusive
    for (int i = lo; i < hi; i++) { g_rowstart[i] = run; run += g_degin[i]; }
    for (int i = t; i < n; i += 1024) {
        g_cs[i] = rsqrtf((float)(g_degout[i] + 1));
        g_cd[i] = rsqrtf((float)(g_degin[i] + 1));
    }
}

__global__ void fill_csr_kernel(const int* __restrict__ src,
                                const int* __restrict__ dst, int e) {
    int i = blockIdx.x * blockDim.x + threadIdx.x;
    if (i < e) {
        int d = dst[i];
        int pos = atomicAdd(&g_cursor[d], 1);
        g_csr[g_rowstart[d] + pos] = src[i];
    }
}

// ---------------------------------------------------------------------------
// Gather: agg[node] = tf32( cd[node] * ( hs[node](*cs) + sum_in hs[src](*cs) ) )
// CS_IN=true only for layer 0 (raw x input); later layers read pre-scaled hs.
// One warp per node, 256 thr/block, high occupancy (latency-bound random reads).
// ---------------------------------------------------------------------------
template <bool CS_IN>
__global__ void __launch_bounds__(256)
gather_kernel(const float* __restrict__ h, int n) {
    int w = (blockIdx.x * blockDim.x + threadIdx.x) >> 5;
    int lane = threadIdx.x & 31;
    if (w >= n) return;
    int node = w;
    int base = g_rowstart[node];
    int deg  = g_degin[node];

    float4 acc = __ldg((const float4*)h + (size_t)node * 32 + lane);
    if (CS_IN) {
        float c = g_cs[node];
        acc.x *= c; acc.y *= c; acc.z *= c; acc.w *= c;
    }

    for (int j0 = 0; j0 < deg; j0 += 32) {
        int cnt = min(32, deg - j0);
        int sj = 0; float cj = 0.0f;
        if (lane < cnt) {
            sj = __ldg(&g_csr[base + j0 + lane]);
            if (CS_IN) cj = g_cs[sj];
        }
        int k = 0;
        for (; k + 4 <= cnt; k += 4) {
            int s0 = __shfl_sync(0xffffffffu, sj, k);
            int s1 = __shfl_sync(0xffffffffu, sj, k + 1);
            int s2 = __shfl_sync(0xffffffffu, sj, k + 2);
            int s3 = __shfl_sync(0xffffffffu, sj, k + 3);
            float4 v0 = __ldg((const float4*)h + (size_t)s0 * 32 + lane);
            float4 v1 = __ldg((const float4*)h + (size_t)s1 * 32 + lane);
            float4 v2 = __ldg((const float4*)h + (size_t)s2 * 32 + lane);
            float4 v3 = __ldg((const float4*)h + (size_t)s3 * 32 + lane);
            if (CS_IN) {
                float c0 = __shfl_sync(0xffffffffu, cj, k);
                float c1 = __shfl_sync(0xffffffffu, cj, k + 1);
                float c2 = __shfl_sync(0xffffffffu, cj, k + 2);
                float c3 = __shfl_sync(0xffffffffu, cj, k + 3);
                acc.x += v0.x * c0; acc.y += v0.y * c0; acc.z += v0.z * c0; acc.w += v0.w * c0;
                acc.x += v1.x * c1; acc.y += v1.y * c1; acc.z += v1.z * c1; acc.w += v1.w * c1;
                acc.x += v2.x * c2; acc.y += v2.y * c2; acc.z += v2.z * c2; acc.w += v2.w * c2;
                acc.x += v3.x * c3; acc.y += v3.y * c3; acc.z += v3.z * c3; acc.w += v3.w * c3;
            } else {
                acc.x += v0.x + v1.x + v2.x + v3.x;
                acc.y += v0.y + v1.y + v2.y + v3.y;
                acc.z += v0.z + v1.z + v2.z + v3.z;
                acc.w += v0.w + v1.w + v2.w + v3.w;
            }
        }
        for (; k < cnt; k++) {
            int s0 = __shfl_sync(0xffffffffu, sj, k);
            float4 v0 = __ldg((const float4*)h + (size_t)s0 * 32 + lane);
            if (CS_IN) {
                float c0 = __shfl_sync(0xffffffffu, cj, k);
                acc.x += v0.x * c0; acc.y += v0.y * c0; acc.z += v0.z * c0; acc.w += v0.w * c0;
            } else {
                acc.x += v0.x; acc.y += v0.y; acc.z += v0.z; acc.w += v0.w;
            }
        }
    }

    float cdv = g_cd[node];
    acc.x = to_tf32(acc.x * cdv); acc.y = to_tf32(acc.y * cdv);
    acc.z = to_tf32(acc.z * cdv); acc.w = to_tf32(acc.w * cdv);
    ((float4*)g_agg)[(size_t)node * 32 + lane] = acc;
}

// ---------------------------------------------------------------------------
// Tensor-core GEMM (portable mma.sync tf32 m16n8k8).
// out = relu(agg @ W + b) [* cs[row] if cs_out]. One CTA per 128 rows, 8 warps
// each 32(M)x64(N). agg already tf32-rounded -> A staging is a plain copy.
// ---------------------------------------------------------------------------
#define GSTR 132
#define GT_SMEM (2 * 128 * GSTR * 4)

__global__ void __launch_bounds__(256, 1)
gemm_mma_kernel(const float* __restrict__ wt, const float* __restrict__ b,
                float* __restrict__ out, int n, int cs_out) {
    extern __shared__ float sh[];
    float* Bsm = sh;               // 128 x GSTR : Wt[n][k]
    float* Asm = sh + 128 * GSTR;  // 128 x GSTR : A[m][k]

    int t = threadIdx.x;
    int rows0 = blockIdx.x * 128;

#pragma unroll
    for (int it = 0; it < 16; it++) {
        int e4 = t + it * 256;
        int r = e4 >> 5, kq = e4 & 31;
        *(float4*)&Bsm[r * GSTR + kq * 4] = __ldg((const float4*)wt + e4);
    }
#pragma unroll
    for (int it = 0; it < 16; it++) {
        int e4 = t + it * 256;
        int r = e4 >> 5, kq = e4 & 31;
        int gr = rows0 + r;
        if (gr > n - 1) gr = n - 1;
        *(float4*)&Asm[r * GSTR + kq * 4] = __ldg((const float4*)g_agg + (size_t)gr * 32 + kq);
    }
    __syncthreads();

    int wid = t >> 5, lane = t & 31;
    int groupID = lane >> 2, ktid = lane & 3;
    int warpM = (wid & 3) * 32;
    int warpN = (wid >> 2) * 64;

    float acc[2][8][4];
#pragma unroll
    for (int mt = 0; mt < 2; mt++)
#pragma unroll
        for (int nt = 0; nt < 8; nt++)
#pragma unroll
            for (int q = 0; q < 4; q++) acc[mt][nt][q] = 0.0f;

#pragma unroll
    for (int k0 = 0; k0 < 128; k0 += 8) {
        uint32_t a[2][4];
#pragma unroll
        for (int mt = 0; mt < 2; mt++) {
            int r0 = warpM + mt * 16 + groupID;
            a[mt][0] = __float_as_uint(Asm[r0 * GSTR + k0 + ktid]);
            a[mt][1] = __float_as_uint(Asm[(r0 + 8) * GSTR + k0 + ktid]);
            a[mt][2] = __float_as_uint(Asm[r0 * GSTR + k0 + ktid + 4]);
            a[mt][3] = __float_as_uint(Asm[(r0 + 8) * GSTR + k0 + ktid + 4]);
        }
#pragma unroll
        for (int nt = 0; nt < 8; nt++) {
            int c0 = warpN + nt * 8 + groupID;
            uint32_t b0 = __float_as_uint(Bsm[c0 * GSTR + k0 + ktid]);
            uint32_t b1 = __float_as_uint(Bsm[c0 * GSTR + k0 + ktid + 4]);
#pragma unroll
            for (int mt = 0; mt < 2; mt++) {
                asm volatile(
                    "mma.sync.aligned.m16n8k8.row.col.f32.tf32.tf32.f32 "
                    "{%0,%1,%2,%3}, {%4,%5,%6,%7}, {%8,%9}, {%0,%1,%2,%3};"
                    : "+f"(acc[mt][nt][0]), "+f"(acc[mt][nt][1]),
                      "+f"(acc[mt][nt][2]), "+f"(acc[mt][nt][3])
                    : "r"(a[mt][0]), "r"(a[mt][1]), "r"(a[mt][2]), "r"(a[mt][3]),
                      "r"(b0), "r"(b1));
            }
        }
    }

    // Epilogue: bias + relu (+ optional cs[row] fold for the next gather)
#pragma unroll
    for (int mt = 0; mt < 2; mt++) {
        int r0 = rows0 + warpM + mt * 16 + groupID;
        int r1 = r0 + 8;
        float sc0 = 1.0f, sc1 = 1.0f;
        if (cs_out) {
            if (r0 < n) sc0 = g_cs[r0];
            if (r1 < n) sc1 = g_cs[r1];
        }
#pragma unroll
        for (int nt = 0; nt < 8; nt++) {
            int col = warpN + nt * 8 + 2 * ktid;
            float2 bb = __ldg((const float2*)(b + col));
            if (r0 < n) {
                float2 o;
                o.x = fmaxf(acc[mt][nt][0] + bb.x, 0.0f) * sc0;
                o.y = fmaxf(acc[mt][nt][1] + bb.y, 0.0f) * sc0;
                *(float2*)(out + (size_t)r0 * DD + col) = o;
            }
            if (r1 < n) {
                float2 o;
                o.x = fmaxf(acc[mt][nt][2] + bb.x, 0.0f) * sc1;
                o.y = fmaxf(acc[mt][nt][3] + bb.y, 0.0f) * sc1;
                *(float2*)(out + (size_t)r1 * DD + col) = o;
            }
        }
    }
}

// ---------------------------------------------------------------------------
// Pooling: graph_ids sorted -> run-based accumulation, flush per run.
// ---------------------------------------------------------------------------
__global__ void pool_kernel(const float* __restrict__ h,
                            const int* __restrict__ gid, int n) {
    int w = (blockIdx.x * blockDim.x + threadIdx.x) >> 5;
    int lane = threadIdx.x & 31;
    int n0 = w * 16;
    if (n0 >= n) return;
    int n1 = min(n0 + 16, n);

    float4 acc = make_float4(0.f, 0.f, 0.f, 0.f);
    int curg = gid[n0];
    int cnt = 0;
    for (int node = n0; node < n1; node++) {
        int g = gid[node];
        if (g != curg) {
            float* o = g_sums + curg * DD + lane * 4;
            asm volatile("red.global.add.v4.f32 [%0], {%1, %2, %3, %4};"
                         :: "l"(o), "f"(acc.x), "f"(acc.y), "f"(acc.z), "f"(acc.w)
                         : "memory");
            if (lane == 0) atomicAdd(&g_cnt[curg], (float)cnt);
            acc = make_float4(0.f, 0.f, 0.f, 0.f);
            curg = g; cnt = 0;
        }
        float4 v = __ldg((const float4*)h + (size_t)node * 32 + lane);
        acc.x += v.x; acc.y += v.y; acc.z += v.z; acc.w += v.w;
        cnt++;
    }
    float* o = g_sums + curg * DD + lane * 4;
    asm volatile("red.global.add.v4.f32 [%0], {%1, %2, %3, %4};"
                 :: "l"(o), "f"(acc.x), "f"(acc.y), "f"(acc.z), "f"(acc.w)
                 : "memory");
    if (lane == 0) atomicAdd(&g_cnt[curg], (float)cnt);
}

__global__ void divide_kernel(float* __restrict__ out) {
    int i = blockIdx.x * blockDim.x + threadIdx.x;
    if (i < GG * DD) out[i] = g_sums[i] / fmaxf(g_cnt[i >> 7], 1.0f);
}

// ---------------------------------------------------------------------------
extern "C" void kernel_launch(void* const* d_in, const int* in_sizes, int n_in,
                              void* d_out, int out_size) {
    const float* x  = (const float*)d_in[0];
    const float* Ws[3] = {(const float*)d_in[1], (const float*)d_in[3], (const float*)d_in[5]};
    const float* bs[3] = {(const float*)d_in[2], (const float*)d_in[4], (const float*)d_in[6]};
    const int* src = (const int*)d_in[7];
    const int* dst = (const int*)d_in[8];
    const int* gid = (const int*)d_in[9];

    int n = in_sizes[0] / DD;          // 100000
    int e = in_sizes[7];               // 1600000

    cudaFuncSetAttribute(gemm_mma_kernel,
                         cudaFuncAttributeMaxDynamicSharedMemorySize, GT_SMEM);

    void* p0; cudaGetSymbolAddress(&p0, g_h0);
    void* p1; cudaGetSymbolAddress(&p1, g_h1);
    void* p2; cudaGetSymbolAddress(&p2, g_h2);
    void* pw; cudaGetSymbolAddress(&pw, g_wt);
    float* h0 = (float*)p0;
    float* h1 = (float*)p1;
    float* h2 = (float*)p2;
    float* wt = (float*)pw;

    setup_kernel<<<(n + 255) / 256, 256>>>(Ws[0], Ws[1], Ws[2], n);
    count_deg_kernel<<<(e + 255) / 256, 256>>>(src, dst, e);
    norm_scan_kernel<<<1, 1024>>>(n);
    fill_csr_kernel<<<(e + 255) / 256, 256>>>(src, dst, e);

    int gtiles = (n + 127) / 128;
    int gblocks = (int)(((size_t)n * 32 + 255) / 256);

    // layer 0: raw x input (cs applied per edge), output pre-scaled by cs
    gather_kernel<true><<<gblocks, 256>>>(x, n);
    gemm_mma_kernel<<<gtiles, 256, GT_SMEM>>>(wt, bs[0], h0, n, 1);
    // layer 1: pre-scaled input, output pre-scaled by cs
    gather_kernel<false><<<gblocks, 256>>>(h0, n);
    gemm_mma_kernel<<<gtiles, 256, GT_SMEM>>>(wt + DD * DD, bs[1], h1, n, 1);
    // layer 2: pre-scaled input, raw output for pooling
    gather_kernel<false><<<gblocks, 256>>>(h1, n);
    gemm_mma_kernel<<<gtiles, 256, GT_SMEM>>>(wt + 2 * DD * DD, bs[2], h2, n, 0);

    pool_kernel<<<(n + 127) / 128, 256>>>(h2, gid, n);
    divide_kernel<<<(GG * DD + 255) / 256, 256>>>((float*)d_out);
}

// round 8
// speedup vs baseline: 1.5061x; 1.1679x over previous
#include <cuda_runtime.h>
#include <cuda_fp16.h>
#include <cuda_bf16.h>
#include <cstdint>

#define NN 100000
#define DD 128
#define GG 64

// Scratch (__device__ globals; no allocation allowed)
__device__ __align__(16) __half g_xh[NN * DD];     // x * cs, fp16
__device__ __align__(16) __half g_h0[NN * DD];     // layer outputs (fp16)
__device__ __align__(16) __half g_h1[NN * DD];
__device__ __align__(16) __half g_h2[NN * DD];
__device__ __align__(16) __half g_agg[NN * DD];    // gathered+cd-scaled rows (fp16)
__device__ __align__(16) __half g_wt[3 * DD * DD]; // W transposed + fp16: wt[l][n][k]
__device__ float g_cs[NN];
__device__ float g_cd[NN];
__device__ int   g_degout[NN];
__device__ int   g_degin[NN];
__device__ int   g_rowstart[NN];
__device__ int   g_cursor[NN];
__device__ int   g_csr[1700000];
__device__ __align__(16) float g_sums[GG * DD];
__device__ float g_cnt[GG];

// ---------------------------------------------------------------------------
// Setup: zero int arrays + pool accumulators, prep all 3 W (transpose + fp16)
// ---------------------------------------------------------------------------
__global__ void setup_kernel(const float* __restrict__ W0, const float* __restrict__ W1,
                             const float* __restrict__ W2, int n) {
    int i = blockIdx.x * blockDim.x + threadIdx.x;
    if (i < n) { g_degout[i] = 0; g_degin[i] = 0; g_cursor[i] = 0; }
    if (i < 3 * DD * DD) {
        const float* W = (i < DD * DD) ? W0 : ((i < 2 * DD * DD) ? W1 : W2);
        int j = i & (DD * DD - 1);
        int k = j >> 7, nn = j & 127;
        g_wt[(i >> 14) * DD * DD + nn * DD + k] = __float2half(W[j]);
    }
    if (i < GG * DD) g_sums[i] = 0.0f;
    if (i < GG) g_cnt[i] = 0.0f;
}

__global__ void count_deg_kernel(const int* __restrict__ src,
                                 const int* __restrict__ dst, int e) {
    int i = blockIdx.x * blockDim.x + threadIdx.x;
    if (i < e) {
        atomicAdd(&g_degout[src[i]], 1);
        atomicAdd(&g_degin[dst[i]], 1);
    }
}

// Single-CTA scan over degin -> rowstart, plus norms. 1024 threads.
__global__ void norm_scan_kernel(int n) {
    __shared__ int s[1024];
    int t = threadIdx.x;
    int chunk = (n + 1023) >> 10;
    int lo = min(t * chunk, n), hi = min(lo + chunk, n);
    int sum = 0;
    for (int i = lo; i < hi; i++) sum += g_degin[i];
    s[t] = sum;
    __syncthreads();
#pragma unroll
    for (int off = 1; off < 1024; off <<= 1) {
        int add = (t >= off) ? s[t - off] : 0;
        __syncthreads();
        s[t] += add;
        __syncthreads();
    }
    int run = s[t] - sum;   // exclusive
    for (int i = lo; i < hi; i++) { g_rowstart[i] = run; run += g_degin[i]; }
    for (int i = t; i < n; i += 1024) {
        g_cs[i] = rsqrtf((float)(g_degout[i] + 1));
        g_cd[i] = rsqrtf((float)(g_degin[i] + 1));
    }
}

__global__ void fill_csr_kernel(const int* __restrict__ src,
                                const int* __restrict__ dst, int e) {
    int i = blockIdx.x * blockDim.x + threadIdx.x;
    if (i < e) {
        int d = dst[i];
        int pos = atomicAdd(&g_cursor[d], 1);
        g_csr[g_rowstart[d] + pos] = src[i];
    }
}

// xh[node] = half(x[node] * cs[node]); one thread per float4 quad
__global__ void prep_x_kernel(const float* __restrict__ x, int n) {
    int i = blockIdx.x * blockDim.x + threadIdx.x;
    if (i >= n * 32) return;
    int node = i >> 5, q = i & 31;
    float c = g_cs[node];
    float4 v = __ldg((const float4*)x + (size_t)node * 32 + q);
    uint2 o;
    *(__half2*)&o.x = __float22half2_rn(make_float2(v.x * c, v.y * c));
    *(__half2*)&o.y = __float22half2_rn(make_float2(v.z * c, v.w * c));
    ((uint2*)g_xh)[(size_t)node * 32 + q] = o;
}

// ---------------------------------------------------------------------------
// Gather: agg[node] = half( cd[node] * ( hs[node] + sum_in hs[src] ) )
// Inputs are pre-scaled by cs. fp16 rows: one uint2 (4 halfs) per lane.
// One warp per node, unroll 8 edges for MLP.
// ---------------------------------------------------------------------------
__global__ void __launch_bounds__(256)
gather_kernel(const __half* __restrict__ h, int n) {
    int w = (blockIdx.x * blockDim.x + threadIdx.x) >> 5;
    int lane = threadIdx.x & 31;
    if (w >= n) return;
    int node = w;
    int base = g_rowstart[node];
    int deg  = g_degin[node];

    uint2 sv = __ldg((const uint2*)h + (size_t)node * 32 + lane);
    float2 f0 = __half22float2(*(__half2*)&sv.x);
    float2 f1 = __half22float2(*(__half2*)&sv.y);
    float4 acc = make_float4(f0.x, f0.y, f1.x, f1.y);

    for (int j0 = 0; j0 < deg; j0 += 32) {
        int cnt = min(32, deg - j0);
        int sj = (lane < cnt) ? __ldg(&g_csr[base + j0 + lane]) : 0;
        int k = 0;
        for (; k + 8 <= cnt; k += 8) {
            int s[8];
#pragma unroll
            for (int u = 0; u < 8; u++) s[u] = __shfl_sync(0xffffffffu, sj, k + u);
            uint2 v[8];
#pragma unroll
            for (int u = 0; u < 8; u++)
                v[u] = __ldg((const uint2*)h + (size_t)s[u] * 32 + lane);
#pragma unroll
            for (int u = 0; u < 8; u++) {
                float2 a0 = __half22float2(*(__half2*)&v[u].x);
                float2 a1 = __half22float2(*(__half2*)&v[u].y);
                acc.x += a0.x; acc.y += a0.y; acc.z += a1.x; acc.w += a1.y;
            }
        }
        for (; k < cnt; k++) {
            int s0 = __shfl_sync(0xffffffffu, sj, k);
            uint2 v0 = __ldg((const uint2*)h + (size_t)s0 * 32 + lane);
            float2 a0 = __half22float2(*(__half2*)&v0.x);
            float2 a1 = __half22float2(*(__half2*)&v0.y);
            acc.x += a0.x; acc.y += a0.y; acc.z += a1.x; acc.w += a1.y;
        }
    }

    float cdv = g_cd[node];
    uint2 o;
    *(__half2*)&o.x = __float22half2_rn(make_float2(acc.x * cdv, acc.y * cdv));
    *(__half2*)&o.y = __float22half2_rn(make_float2(acc.z * cdv, acc.w * cdv));
    ((uint2*)g_agg)[(size_t)node * 32 + lane] = o;
}

// ---------------------------------------------------------------------------
// Tensor-core GEMM, fp16 inputs / fp32 accum (mma.sync m16n8k16).
// out = half( relu(agg @ W + b) [* cs[row]] ). One CTA per 128 rows, 8 warps
// each 32(M)x64(N). Smem stride 136 halfs -> conflict-free fragment loads.
// ---------------------------------------------------------------------------
#define ASTR 136
#define GT_SMEM (2 * 128 * ASTR * 2)

__global__ void __launch_bounds__(256, 1)
gemm_mma_kernel(const __half* __restrict__ wt, const float* __restrict__ b,
                __half* __restrict__ out, int n, int cs_out) {
    extern __shared__ __half sh[];
    __half* Bsm = sh;               // 128 x ASTR : Wt[n][k]
    __half* Asm = sh + 128 * ASTR;  // 128 x ASTR : A[m][k]

    int t = threadIdx.x;
    int rows0 = blockIdx.x * 128;

    // Stage Wt + A: 2048 uint4 each (16 uint4 per 128-half row)
#pragma unroll
    for (int it = 0; it < 8; it++) {
        int idx = t + it * 256;
        int r = idx >> 4, c = idx & 15;
        *(uint4*)&Bsm[r * ASTR + c * 8] = __ldg((const uint4*)wt + idx);
    }
#pragma unroll
    for (int it = 0; it < 8; it++) {
        int idx = t + it * 256;
        int r = idx >> 4, c = idx & 15;
        int gr = rows0 + r;
        if (gr > n - 1) gr = n - 1;
        *(uint4*)&Asm[r * ASTR + c * 8] = __ldg((const uint4*)(g_agg + (size_t)gr * DD) + c);
    }
    __syncthreads();

    int wid = t >> 5, lane = t & 31;
    int groupID = lane >> 2, ktid = lane & 3;
    int warpM = (wid & 3) * 32;
    int warpN = (wid >> 2) * 64;

    float acc[2][8][4];
#pragma unroll
    for (int mt = 0; mt < 2; mt++)
#pragma unroll
        for (int nt = 0; nt < 8; nt++)
#pragma unroll
            for (int q = 0; q < 4; q++) acc[mt][nt][q] = 0.0f;

#pragma unroll
    for (int k0 = 0; k0 < 128; k0 += 16) {
        uint32_t a[2][4];
#pragma unroll
        for (int mt = 0; mt < 2; mt++) {
            int r0 = warpM + mt * 16 + groupID;
            a[mt][0] = *(const uint32_t*)&Asm[r0 * ASTR + k0 + ktid * 2];
            a[mt][1] = *(const uint32_t*)&Asm[(r0 + 8) * ASTR + k0 + ktid * 2];
            a[mt][2] = *(const uint32_t*)&Asm[r0 * ASTR + k0 + ktid * 2 + 8];
            a[mt][3] = *(const uint32_t*)&Asm[(r0 + 8) * ASTR + k0 + ktid * 2 + 8];
        }
#pragma unroll
        for (int nt = 0; nt < 8; nt++) {
            int c0 = warpN + nt * 8 + groupID;
            uint32_t b0 = *(const uint32_t*)&Bsm[c0 * ASTR + k0 + ktid * 2];
            uint32_t b1 = *(const uint32_t*)&Bsm[c0 * ASTR + k0 + ktid * 2 + 8];
#pragma unroll
            for (int mt = 0; mt < 2; mt++) {
                asm volatile(
                    "mma.sync.aligned.m16n8k16.row.col.f32.f16.f16.f32 "
                    "{%0,%1,%2,%3}, {%4,%5,%6,%7}, {%8,%9}, {%0,%1,%2,%3};"
                    : "+f"(acc[mt][nt][0]), "+f"(acc[mt][nt][1]),
                      "+f"(acc[mt][nt][2]), "+f"(acc[mt][nt][3])
                    : "r"(a[mt][0]), "r"(a[mt][1]), "r"(a[mt][2]), "r"(a[mt][3]),
                      "r"(b0), "r"(b1));
            }
        }
    }

    // Epilogue: bias + relu (+ optional cs fold), fp16 stores
#pragma unroll
    for (int mt = 0; mt < 2; mt++) {
        int r0 = rows0 + warpM + mt * 16 + groupID;
        int r1 = r0 + 8;
        float sc0 = 1.0f, sc1 = 1.0f;
        if (cs_out) {
            if (r0 < n) sc0 = g_cs[r0];
            if (r1 < n) sc1 = g_cs[r1];
        }
#pragma unroll
        for (int nt = 0; nt < 8; nt++) {
            int col = warpN + nt * 8 + 2 * ktid;
            float2 bb = __ldg((const float2*)(b + col));
            if (r0 < n) {
                float2 o = make_float2(fmaxf(acc[mt][nt][0] + bb.x, 0.0f) * sc0,
                                       fmaxf(acc[mt][nt][1] + bb.y, 0.0f) * sc0);
                *(__half2*)(out + (size_t)r0 * DD + col) = __float22half2_rn(o);
            }
            if (r1 < n) {
                float2 o = make_float2(fmaxf(acc[mt][nt][2] + bb.x, 0.0f) * sc1,
                                       fmaxf(acc[mt][nt][3] + bb.y, 0.0f) * sc1);
                *(__half2*)(out + (size_t)r1 * DD + col) = __float22half2_rn(o);
            }
        }
    }
}

// ---------------------------------------------------------------------------
// Pooling: graph_ids sorted -> run-based accumulation, flush per run.
// ---------------------------------------------------------------------------
__global__ void pool_kernel(const __half* __restrict__ h,
                            const int* __restrict__ gid, int n) {
    int w = (blockIdx.x * blockDim.x + threadIdx.x) >> 5;
    int lane = threadIdx.x & 31;
    int n0 = w * 16;
    if (n0 >= n) return;
    int n1 = min(n0 + 16, n);

    float4 acc = make_float4(0.f, 0.f, 0.f, 0.f);
    int curg = gid[n0];
    int cnt = 0;
    for (int node = n0; node < n1; node++) {
        int g = gid[node];
        if (g != curg) {
            float* o = g_sums + curg * DD + lane * 4;
            asm volatile("red.global.add.v4.f32 [%0], {%1, %2, %3, %4};"
                         :: "l"(o), "f"(acc.x), "f"(acc.y), "f"(acc.z), "f"(acc.w)
                         : "memory");
            if (lane == 0) atomicAdd(&g_cnt[curg], (float)cnt);
            acc = make_float4(0.f, 0.f, 0.f, 0.f);
            curg = g; cnt = 0;
        }
        uint2 v = __ldg((const uint2*)h + (size_t)node * 32 + lane);
        float2 a0 = __half22float2(*(__half2*)&v.x);
        float2 a1 = __half22float2(*(__half2*)&v.y);
        acc.x += a0.x; acc.y += a0.y; acc.z += a1.x; acc.w += a1.y;
        cnt++;
    }
    float* o = g_sums + curg * DD + lane * 4;
    asm volatile("red.global.add.v4.f32 [%0], {%1, %2, %3, %4};"
                 :: "l"(o), "f"(acc.x), "f"(acc.y), "f"(acc.z), "f"(acc.w)
                 : "memory");
    if (lane == 0) atomicAdd(&g_cnt[curg], (float)cnt);
}

__global__ void divide_kernel(float* __restrict__ out) {
    int i = blockIdx.x * blockDim.x + threadIdx.x;
    if (i < GG * DD) out[i] = g_sums[i] / fmaxf(g_cnt[i >> 7], 1.0f);
}

// ---------------------------------------------------------------------------
extern "C" void kernel_launch(void* const* d_in, const int* in_sizes, int n_in,
                              void* d_out, int out_size) {
    const float* x  = (const float*)d_in[0];
    const float* Ws[3] = {(const float*)d_in[1], (const float*)d_in[3], (const float*)d_in[5]};
    const float* bs[3] = {(const float*)d_in[2], (const float*)d_in[4], (const float*)d_in[6]};
    const int* src = (const int*)d_in[7];
    const int* dst = (const int*)d_in[8];
    const int* gid = (const int*)d_in[9];

    int n = in_sizes[0] / DD;          // 100000
    int e = in_sizes[7];               // 1600000

    cudaFuncSetAttribute(gemm_mma_kernel,
                         cudaFuncAttributeMaxDynamicSharedMemorySize, GT_SMEM);

    void* pxh; cudaGetSymbolAddress(&pxh, g_xh);
    void* p0;  cudaGetSymbolAddress(&p0, g_h0);
    void* p1;  cudaGetSymbolAddress(&p1, g_h1);
    void* p2;  cudaGetSymbolAddress(&p2, g_h2);
    void* pw;  cudaGetSymbolAddress(&pw, g_wt);
    __half* xh = (__half*)pxh;
    __half* h0 = (__half*)p0;
    __half* h1 = (__half*)p1;
    __half* h2 = (__half*)p2;
    __half* wt = (__half*)pw;

    setup_kernel<<<(n + 255) / 256, 256>>>(Ws[0], Ws[1], Ws[2], n);
    count_deg_kernel<<<(e + 255) / 256, 256>>>(src, dst, e);
    norm_scan_kernel<<<1, 1024>>>(n);
    fill_csr_kernel<<<(e + 255) / 256, 256>>>(src, dst, e);
    prep_x_kernel<<<(int)(((size_t)n * 32 + 255) / 256), 256>>>(x, n);

    int gtiles = (n + 127) / 128;
    int gblocks = (int)(((size_t)n * 32 + 255) / 256);

    gather_kernel<<<gblocks, 256>>>(xh, n);
    gemm_mma_kernel<<<gtiles, 256, GT_SMEM>>>(wt, bs[0], h0, n, 1);
    gather_kernel<<<gblocks, 256>>>(h0, n);
    gemm_mma_kernel<<<gtiles, 256, GT_SMEM>>>(wt + DD * DD, bs[1], h1, n, 1);
    gather_kernel<<<gblocks, 256>>>(h1, n);
    gemm_mma_kernel<<<gtiles, 256, GT_SMEM>>>(wt + 2 * DD * DD, bs[2], h2, n, 0);

    pool_kernel<<<(n + 127) / 128, 256>>>(h2, gid, n);
    divide_kernel<<<(GG * DD + 255) / 256, 256>>>((float*)d_out);
}